// round 8
// baseline (speedup 1.0000x reference)
#include <cuda_runtime.h>
#include <cuda_bf16.h>

#define EPS 1e-12f

__device__ __forceinline__ float sel4(float4 q, int r) {
    float v = q.x;
    if (r == 1) v = q.y;
    if (r == 2) v = q.z;
    if (r == 3) v = q.w;
    return v;
}

// Load the adjacent pair (vrow[i], vrow[i+1]) with one aligned LDG.128,
// plus a predicated scalar fixup when the pair straddles a 16B boundary.
__device__ __forceinline__ float2 pair_ld(const float* __restrict__ vrow, int i) {
    int base = i & ~3;
    int r    = i & 3;
    float4 q = __ldg(reinterpret_cast<const float4*>(vrow + base));
    float v0 = sel4(q, r);
    float v1 = sel4(q, min(r + 1, 3));
    if (r == 3) v1 = __ldg(vrow + i + 1);
    return make_float2(v0, v1);
}

__global__ __launch_bounds__(256)
void timing_prop_kernel(const float* __restrict__ x_t_arr,
                        const float* __restrict__ x_c_arr,
                        const int*   __restrict__ arc_idxs,
                        const float* __restrict__ vals,
                        const float* __restrict__ t_tbl,
                        const float* __restrict__ c_tbl,
                        const int*   __restrict__ dims,
                        float*       __restrict__ out,
                        int B)
{
    int b = blockIdx.x * blockDim.x + threadIdx.x;
    if (b >= B) return;

    // streamed, zero-reuse -> evict-first (keep L2 for tables/values)
    float x_t = __ldcs(x_t_arr + b);
    float x_c = __ldcs(x_c_arr + b);
    int   a   = __ldcs(arc_idxs + b);

    // dims gather (hot, keep cached)
    int2 d = __ldg(reinterpret_cast<const int2*>(dims) + a);
    int td = d.x, cd = d.y;

    if (td <= 0 || cd <= 0) { __stcs(out + b, 0.0f); return; }

    bool need_t = (td > 1);
    bool need_c = (cd > 1);

    // table gathers, PREDICATED: when dim<=1 that table never affects the
    // result (indices clamp to 0, fraction is hidden by the degenerate
    // select), so skip the loads -> fewer L1 wavefronts + fewer DRAM sectors.
    const float4* tt4 = reinterpret_cast<const float4*>(t_tbl) + 2 * a;
    const float4* ct4 = reinterpret_cast<const float4*>(c_tbl) + 2 * a;
    float4 tA = make_float4(0.f, 0.f, 0.f, 0.f), tB = tA;
    float4 cA = tA, cB = tA;
    if (need_t) { tA = __ldg(tt4); tB = __ldg(tt4 + 1); }
    if (need_c) { cA = __ldg(ct4); cB = __ldg(ct4 + 1); }

    float tv[8] = {tA.x, tA.y, tA.z, tA.w, tB.x, tB.y, tB.z, tB.w};
    float cv[8] = {cA.x, cA.y, cA.z, cA.w, cB.x, cB.y, cB.z, cB.w};

    // searchsorted side='right' = count of (tbl <= x). Harmless garbage when
    // the table was skipped: the clamp to max(dim-1,0)=0 kills it.
    int ss_t = 0, ss_c = 0;
    #pragma unroll
    for (int j = 0; j < 8; ++j) {
        ss_t += (tv[j] <= x_t) ? 1 : 0;
        ss_c += (cv[j] <= x_c) ? 1 : 0;
    }

    int max_t = max(td - 1, 0);
    int max_c = max(cd - 1, 0);
    // clamp(min=1) then clamp(max=dim-1), matching reference order
    int t_hi = min(max(ss_t, 1), max_t);
    int c_hi = min(max(ss_c, 1), max_c);
    int t_lo = max(t_hi - 1, 0);   // == t_hi-1 whenever td>1
    int c_lo = max(c_hi - 1, 0);   // == c_hi-1 whenever cd>1

    // register-resident breakpoint selection (SEL chains)
    float t0 = tv[0], t1 = tv[0], c0 = cv[0], c1 = cv[0];
    #pragma unroll
    for (int j = 1; j < 8; ++j) {
        if (t_lo == j) t0 = tv[j];
        if (t_hi == j) t1 = tv[j];
        if (c_lo == j) c0 = cv[j];
        if (c_hi == j) c1 = cv[j];
    }

    float ti = t1 - t0;
    float ci = c1 - c0;
    bool t_deg = fabsf(ti) < EPS;
    bool c_deg = fabsf(ci) < EPS;

    float xt = fminf(fmaxf(x_t, t0), t1);
    float xc = fminf(fmaxf(x_c, c0), c1);

    float ti_s = t_deg ? EPS : ti;
    float ci_s = c_deg ? EPS : ci;

    float ft = fminf(fmaxf((xt - t0) / ti_s, 0.0f), 1.0f);
    float fc = fminf(fmaxf((xc - c0) / ci_s, 0.0f), 1.0f);

    const float* vrow = vals + (size_t)a * 64;
    float res;

    if (need_t && need_c) {
        // 2D bilinear. Corners come as two adjacent pairs:
        //   (i00, i00+1) and (i00+cd, i00+cd+1)   [c_hi = c_lo+1, t_hi = t_lo+1]
        int i00 = t_lo * cd + c_lo;
        float2 p0 = pair_ld(vrow, i00);        // v00, v01
        float2 p1 = pair_ld(vrow, i00 + cd);   // v10, v11
        float v00 = p0.x, v01 = p0.y, v10 = p1.x, v11 = p1.y;
        if (t_deg & c_deg) {
            res = v00;
        } else if (t_deg) {
            res = v00 + (v01 - v00) * fc;
        } else if (c_deg) {
            res = v00 + (v10 - v00) * ft;
        } else {
            float wa = (t1 - xt) * (c1 - xc);
            float wb = (t1 - xt) * (xc - c0);
            float wc = (xt - t0) * (c1 - xc);
            float wd = (xt - t0) * (xc - c0);
            res = (v00 * wa + v01 * wb + v10 * wc + v11 * wd) / (ti_s * ci_s);
        }
    } else {
        // Unified 1D-trans / 1D-cap / scalar: exactly one of t_lo/c_lo can be
        // nonzero; the effective fraction replicates the reference's
        // degenerate select (deg -> y0).
        int   i0 = t_lo + c_lo;                 // t_lo (1D-trans) | c_lo (1D-cap) | 0
        float f  = need_t ? (t_deg ? 0.0f : ft)
                          : (c_deg ? 0.0f : fc); // scalar: c table zeroed -> c_deg -> 0
        float2 p = pair_ld(vrow, i0);            // y0, y1 (adjacent; scalar reads [0..3])
        res = p.x + (p.y - p.x) * f;
    }

    __stcs(out + b, res);
}

extern "C" void kernel_launch(void* const* d_in, const int* in_sizes, int n_in,
                              void* d_out, int out_size)
{
    const float* input_trans = (const float*)d_in[0];
    const float* output_caps = (const float*)d_in[1];
    const int*   arc_idxs    = (const int*)d_in[2];
    const float* vals        = (const float*)d_in[3];
    const float* t_tbl       = (const float*)d_in[4];
    const float* c_tbl       = (const float*)d_in[5];
    const int*   dims        = (const int*)d_in[6];
    float*       out         = (float*)d_out;

    int B = in_sizes[0];
    int threads = 256;
    int blocks = (B + threads - 1) / threads;
    timing_prop_kernel<<<blocks, threads>>>(input_trans, output_caps, arc_idxs,
                                            vals, t_tbl, c_tbl, dims, out, B);
}